// round 10
// baseline (speedup 1.0000x reference)
#include <cuda_runtime.h>
#include <cstdint>

// ---------------- problem constants ----------------
#define KNMS 100
#define BMAX 32
#define IOU_THR 0.3f

#define CS13 169
#define CS26 676
#define CS52 2704
#define BASE13 0
#define BASE26 507
#define BASE52 2535
#define LCAP 256            // compact candidate list capacity
#define DBLK 13             // decode blocks per image (13*4 warps >= 52 pairs)

// ---------------- device scratch ----------------
__device__ unsigned long long g_selkey[BMAX * KNMS];  // sorted top-100 keys
__device__ float g_dec[BMAX * KNMS * 6];              // decoded boxes, rank order

__device__ __forceinline__ float sigmoidf_(float x) {
    return 1.0f / (1.0f + expf(-x));
}

// ============================================================
// K1: per-image exact top-100 selection. One block/image, 1024 thr.
// Scores live in 15 register slots; 2 histogram passes pin a 16-bit
// prefix; compact ~140 candidates; exact 64-bit rank = stable sort.
// ============================================================
__global__ void __launch_bounds__(1024)
select_kernel(const float* __restrict__ o13, const float* __restrict__ o26,
              const float* __restrict__ o52, const float* __restrict__ thr_p, int B)
{
    const int b = blockIdx.x;
    const int tid = threadIdx.x;
    const int lane = tid & 31;

    __shared__ unsigned hist[256];
    __shared__ unsigned long long ckey[LCAP];
    __shared__ unsigned srank[LCAP];
    __shared__ unsigned long long selkey[KNMS];
    __shared__ unsigned sh_p0;
    __shared__ int sh_k, sh_cnt;

    const float thr = *thr_p;

    // 15 per-thread score slots in registers
    unsigned sbits[15];
    {
        const float* b13 = o13 + (size_t)b * 255 * CS13;
        const float* b26 = o26 + (size_t)b * 255 * CS26;
        const float* b52 = o52 + (size_t)b * 255 * CS52;
        #pragma unroll
        for (int a = 0; a < 3; ++a) {
            const float* p13 = b13 + (size_t)a * 85 * CS13;
            const float* p26 = b26 + (size_t)a * 85 * CS26;
            const float* p52 = b52 + (size_t)a * 85 * CS52;
            {
                unsigned r = 0;
                if (tid < CS13) { float c = sigmoidf_(p13[tid]); if (c > thr) r = __float_as_uint(c); }
                sbits[a * 5 + 0] = r;
            }
            {
                unsigned r = 0;
                if (tid < CS26) { float c = sigmoidf_(p26[tid]); if (c > thr) r = __float_as_uint(c); }
                sbits[a * 5 + 1] = r;
            }
            #pragma unroll
            for (int j = 0; j < 3; ++j) {
                unsigned r = 0;
                int cell = j * 1024 + tid;
                if (cell < CS52) { float c = sigmoidf_(p52[cell]); if (c > thr) r = __float_as_uint(c); }
                sbits[a * 5 + 2 + j] = r;
            }
        }
    }
    if (tid < 256) hist[tid] = 0u;
    if (tid == 0) { sh_k = KNMS; sh_cnt = 0; }
    __syncthreads();

    // pass 0: top byte
    #pragma unroll
    for (int s = 0; s < 15; ++s) {
        unsigned bits = sbits[s];
        bool act = (bits != 0u);
        unsigned am = __ballot_sync(0xffffffffu, act);
        if (act) {
            unsigned bin = bits >> 24;
            unsigned peers = __match_any_sync(am, bin);
            if (lane == __ffs(peers) - 1)
                atomicAdd(&hist[bin], (unsigned)__popc(peers));
        }
    }
    __syncthreads();
    if (tid < 32) {
        unsigned c[8]; int T = 0;
        #pragma unroll
        for (int r = 0; r < 8; ++r) { c[r] = hist[tid * 8 + r]; T += (int)c[r]; }
        int S = T;
        #pragma unroll
        for (int off = 1; off < 32; off <<= 1) {
            int v = __shfl_down_sync(0xffffffffu, S, off);
            if (tid + off < 32) S += v;
        }
        int Snext = __shfl_down_sync(0xffffffffu, S, 1);
        if (tid == 31) Snext = 0;
        int k = KNMS;
        if (S >= k && Snext < k) {
            int rem = Snext, chosen = 0;
            #pragma unroll
            for (int r = 7; r >= 0; --r) {
                if (rem + (int)c[r] >= k) { chosen = r; break; }
                rem += (int)c[r];
            }
            sh_p0 = (unsigned)(tid * 8 + chosen);
            sh_k = k - rem;
        }
    }
    __syncthreads();
    const unsigned p0 = sh_p0;
    const int k1 = sh_k;
    if (tid < 256) hist[tid] = 0u;
    __syncthreads();

    // pass 1: byte 1 within top-byte bin
    #pragma unroll
    for (int s = 0; s < 15; ++s) {
        unsigned bits = sbits[s];
        bool act = (bits != 0u) && ((bits >> 24) == p0);
        unsigned am = __ballot_sync(0xffffffffu, act);
        if (act) {
            unsigned bin = (bits >> 16) & 0xFF;
            unsigned peers = __match_any_sync(am, bin);
            if (lane == __ffs(peers) - 1)
                atomicAdd(&hist[bin], (unsigned)__popc(peers));
        }
    }
    __syncthreads();
    if (tid < 32) {
        unsigned c[8]; int T = 0;
        #pragma unroll
        for (int r = 0; r < 8; ++r) { c[r] = hist[tid * 8 + r]; T += (int)c[r]; }
        int S = T;
        #pragma unroll
        for (int off = 1; off < 32; off <<= 1) {
            int v = __shfl_down_sync(0xffffffffu, S, off);
            if (tid + off < 32) S += v;
        }
        int Snext = __shfl_down_sync(0xffffffffu, S, 1);
        if (tid == 31) Snext = 0;
        if (S >= k1 && Snext < k1) {
            int rem = Snext, chosen = 0;
            #pragma unroll
            for (int r = 7; r >= 0; --r) {
                if (rem + (int)c[r] >= k1) { chosen = r; break; }
                rem += (int)c[r];
            }
            sh_p0 = (p0 << 8) | (unsigned)(tid * 8 + chosen);
        }
    }
    if (tid < 256) { ckey[tid] = 0ull; srank[tid] = 0u; }
    __syncthreads();
    const unsigned P16 = sh_p0;

    // compact candidates: top16 >= P16
    #pragma unroll
    for (int s = 0; s < 15; ++s) {
        unsigned bits = sbits[s];
        if (bits != 0u && (bits >> 16) >= P16) {
            int a = s / 5, r = s % 5;
            int n;
            if (r == 0)      n = BASE13 + tid * 3 + a;
            else if (r == 1) n = BASE26 + tid * 3 + a;
            else             n = BASE52 + ((r - 2) * 1024 + tid) * 3 + a;
            int pos = atomicAdd(&sh_cnt, 1);
            if (pos < LCAP)
                ckey[pos] = ((unsigned long long)bits << 32) | (unsigned)(~(unsigned)n);
        }
    }
    __syncthreads();

    // exact rank (4 slices of 64 per element)
    {
        int e = tid >> 2, slice = tid & 3;
        unsigned long long mykey = ckey[e];
        if (mykey != 0ull) {
            int cnt = 0;
            int j0 = slice * 64;
            #pragma unroll 16
            for (int j = 0; j < 64; ++j)
                if (ckey[j0 + j] > mykey) cnt++;
            if (cnt) atomicAdd(&srank[e], (unsigned)cnt);
        }
    }
    __syncthreads();
    if (tid < 256) {
        unsigned long long k = ckey[tid];
        if (k != 0ull) {
            unsigned r = srank[tid];
            if (r < KNMS) selkey[r] = k;
        }
    }
    __syncthreads();
    if (tid < KNMS) g_selkey[b * KNMS + tid] = selkey[tid];
}

// ============================================================
// K2: decode gather — 416 CTAs for chip-wide MLP. 128 thr/block,
// one warp handles 2 boxes; all scattered loads issued up front.
// ============================================================
__device__ __forceinline__ void decode_emit(
    int b, int box, int lane, float v0, float v1, float v2,
    int x, int y, float strd, float aw, float ah)
{
    float ch0 = __shfl_sync(0xffffffffu, v0, 0);
    float ch1 = __shfl_sync(0xffffffffu, v0, 1);
    float ch2 = __shfl_sync(0xffffffffu, v0, 2);
    float ch3 = __shfl_sync(0xffffffffu, v0, 3);
    float ch4 = __shfl_sync(0xffffffffu, v0, 4);

    float bv = -3.402823466e+38f;
    int bi = 0x7FFFFFFF;
    if (lane >= 5)            { bv = v0; bi = lane - 5; }
    if (v1 > bv)              { bv = v1; bi = lane + 27; }
    if (lane < 21 && v2 > bv) { bv = v2; bi = lane + 59; }
    #pragma unroll
    for (int off = 16; off; off >>= 1) {
        float ov = __shfl_xor_sync(0xffffffffu, bv, off);
        int oi = __shfl_xor_sync(0xffffffffu, bi, off);
        if (ov > bv || (ov == bv && oi < bi)) { bv = ov; bi = oi; }
    }

    if (lane == 0) {
        float conf = sigmoidf_(ch0);
        float sx = sigmoidf_(ch1);
        float sy = sigmoidf_(ch2);
        float ww = expf(ch3) * aw;
        float hh = expf(ch4) * ah;
        float ox = ((float)x + sx) * strd;
        float oy = ((float)y + sy) * strd;
        float* d = g_dec + ((size_t)b * KNMS + box) * 6;
        d[0] = ox - 0.5f * ww;
        d[1] = oy - 0.5f * hh;
        d[2] = ox + 0.5f * ww;
        d[3] = oy + 0.5f * hh;
        d[4] = (float)bi;
        d[5] = conf;
    }
}

__global__ void __launch_bounds__(128)
decode_kernel(const float* __restrict__ o13, const float* __restrict__ o26,
              const float* __restrict__ o52, const float* __restrict__ anc, int B)
{
    int blk = blockIdx.x;
    int b = blk / DBLK, chunk = blk - b * DBLK;
    int wid = threadIdx.x >> 5, lane = threadIdx.x & 31;
    int pi = chunk * 4 + wid;                 // 0..51
    if (pi >= 52) return;
    int boxA = pi;                            // always < 100
    int boxB = pi + 52;                       // maybe >= 100
    bool hasB = (boxB < KNMS);

    // ---- setup A ----
    unsigned idxA = ~(unsigned)(g_selkey[b * KNMS + boxA] & 0xFFFFFFFFu);
    int SA, csA, baseA; float strdA; const float* inA; const float* arowA;
    if (idxA < BASE26)      { SA = 13; csA = CS13; baseA = BASE13; strdA = 32.f; inA = o13; arowA = anc + 0; }
    else if (idxA < BASE52) { SA = 26; csA = CS26; baseA = BASE26; strdA = 16.f; inA = o26; arowA = anc + 6; }
    else                    { SA = 52; csA = CS52; baseA = BASE52; strdA = 8.f;  inA = o52; arowA = anc + 12; }
    int mA = (int)idxA - baseA;
    int cellA = mA / 3, aA = mA - cellA * 3;
    int yA = cellA / SA, xA = cellA - yA * SA;
    const float* pA = inA + ((size_t)b * 255 + (size_t)aA * 85) * csA + cellA;

    // ---- setup B (mirror A when absent so loads stay valid) ----
    unsigned idxB = hasB ? ~(unsigned)(g_selkey[b * KNMS + boxB] & 0xFFFFFFFFu) : idxA;
    int SB, csB, baseB; float strdB; const float* inB; const float* arowB;
    if (idxB < BASE26)      { SB = 13; csB = CS13; baseB = BASE13; strdB = 32.f; inB = o13; arowB = anc + 0; }
    else if (idxB < BASE52) { SB = 26; csB = CS26; baseB = BASE26; strdB = 16.f; inB = o26; arowB = anc + 6; }
    else                    { SB = 52; csB = CS52; baseB = BASE52; strdB = 8.f;  inB = o52; arowB = anc + 12; }
    int mB = (int)idxB - baseB;
    int cellB = mB / 3, aB = mB - cellB * 3;
    int yB = cellB / SB, xB = cellB - yB * SB;
    const float* pB = inB + ((size_t)b * 255 + (size_t)aB * 85) * csB + cellB;

    // ---- issue all loads up front (max MLP) ----
    float a0 = pA[(size_t)lane * csA];
    float a1 = pA[(size_t)(lane + 32) * csA];
    float a2 = (lane < 21) ? pA[(size_t)(lane + 64) * csA] : 0.f;
    float b0 = pB[(size_t)lane * csB];
    float b1 = pB[(size_t)(lane + 32) * csB];
    float b2 = (lane < 21) ? pB[(size_t)(lane + 64) * csB] : 0.f;

    decode_emit(b, boxA, lane, a0, a1, a2, xA, yA, strdA,
                arowA[aA * 2 + 0], arowA[aA * 2 + 1]);
    if (hasB)
        decode_emit(b, boxB, lane, b0, b1, b2, xB, yB, strdB,
                    arowB[aB * 2 + 0], arowB[aB * 2 + 1]);
}

// ============================================================
// K3: NMS — one block/image, 128 thr. Boxes are L2-hot.
// ============================================================
__global__ void __launch_bounds__(128)
nms_kernel(float* __restrict__ out, int B)
{
    const int b = blockIdx.x;
    const int t = threadIdx.x;

    __shared__ float sbox[KNMS * 6];
    __shared__ float sarea[KNMS];
    __shared__ unsigned sup[KNMS * 4];
    __shared__ unsigned keep0w[4], keepw[4];

    if (t < 4) keep0w[t] = 0u;
    for (int i = t; i < KNMS * 6; i += 128) sbox[i] = g_dec[(size_t)b * KNMS * 6 + i];
    __syncthreads();
    if (t < KNMS) {
        sarea[t] = fmaxf(sbox[t * 6 + 2] - sbox[t * 6 + 0], 0.f) *
                   fmaxf(sbox[t * 6 + 3] - sbox[t * 6 + 1], 0.f);
        if ((unsigned)(g_selkey[b * KNMS + t] >> 32) != 0u)
            atomicOr(&keep0w[t >> 5], 1u << (t & 31));
    }
    __syncthreads();

    for (int w = t; w < KNMS * 4; w += 128) {
        int i = w >> 2, c = w & 3;
        unsigned m = 0;
        float ix1 = sbox[i * 6 + 0], iy1 = sbox[i * 6 + 1];
        float ix2 = sbox[i * 6 + 2], iy2 = sbox[i * 6 + 3];
        float icls = sbox[i * 6 + 4], iar = sarea[i];
        int j0 = c * 32;
        #pragma unroll 8
        for (int jj = 0; jj < 32; ++jj) {
            int j = j0 + jj;
            if (j > i && j < KNMS && sbox[j * 6 + 4] == icls) {
                float x1 = fmaxf(ix1, sbox[j * 6 + 0]);
                float y1 = fmaxf(iy1, sbox[j * 6 + 1]);
                float x2 = fminf(ix2, sbox[j * 6 + 2]);
                float y2 = fminf(iy2, sbox[j * 6 + 3]);
                float inter = fmaxf(x2 - x1, 0.f) * fmaxf(y2 - y1, 0.f);
                float uni = iar + sarea[j] - inter;
                if (inter / fmaxf(uni, 1e-9f) > IOU_THR) m |= (1u << jj);
            }
        }
        sup[w] = m;
    }
    __syncthreads();

    if (t == 0) {
        unsigned k0 = keep0w[0], k1 = keep0w[1], k2 = keep0w[2], k3 = keep0w[3];
        unsigned n0 = sup[0], n1 = sup[1], n2 = sup[2], n3 = sup[3];
        for (int i = 0; i < KNMS; ++i) {
            unsigned s0 = n0, s1 = n1, s2 = n2, s3 = n3;
            if (i + 1 < KNMS) {
                n0 = sup[(i + 1) * 4 + 0];
                n1 = sup[(i + 1) * 4 + 1];
                n2 = sup[(i + 1) * 4 + 2];
                n3 = sup[(i + 1) * 4 + 3];
            }
            unsigned word = (i < 32) ? k0 : (i < 64) ? k1 : (i < 96) ? k2 : k3;
            unsigned msk = (unsigned)(-(int)((word >> (i & 31)) & 1u));
            k0 &= ~(s0 & msk);
            k1 &= ~(s1 & msk);
            k2 &= ~(s2 & msk);
            k3 &= ~(s3 & msk);
        }
        keepw[0] = k0; keepw[1] = k1; keepw[2] = k2; keepw[3] = k3;
    }
    __syncthreads();

    float* out_sel = out;
    float* out_keep = out + (size_t)B * KNMS * 6;
    if (t < KNMS) {
        #pragma unroll
        for (int c = 0; c < 6; ++c)
            out_sel[((size_t)b * KNMS + t) * 6 + c] = sbox[t * 6 + c];
        out_keep[(size_t)b * KNMS + t] =
            ((keepw[t >> 5] >> (t & 31)) & 1u) ? 1.0f : 0.0f;
    }
}

// ============================================================
extern "C" void kernel_launch(void* const* d_in, const int* in_sizes, int n_in,
                              void* d_out, int out_size)
{
    const float* o13 = (const float*)d_in[0];
    const float* o26 = (const float*)d_in[1];
    const float* o52 = (const float*)d_in[2];
    const float* anc = (const float*)d_in[3];   // [3,3,2]
    const float* thr = (const float*)d_in[4];   // scalar

    int B = in_sizes[0] / (255 * CS13);
    if (B > BMAX) B = BMAX;
    float* out = (float*)d_out;

    select_kernel<<<B, 1024>>>(o13, o26, o52, thr, B);
    decode_kernel<<<B * DBLK, 128>>>(o13, o26, o52, anc, B);
    nms_kernel<<<B, 128>>>(out, B);
}

// round 11
// speedup vs baseline: 1.2706x; 1.2706x over previous
#include <cuda_runtime.h>
#include <cstdint>

// ---------------- problem constants ----------------
#define KNMS 100
#define BMAX 32
#define IOU_THR 0.3f

#define CS13 169
#define CS26 676
#define CS52 2704
#define BASE13 0
#define BASE26 507
#define BASE52 2535
#define LCAP 256            // compact candidate list capacity
#define DBLK 13             // decode blocks per image
#define NBIN 4096           // single-pass histogram bins (12-bit monotone key)

// ---------------- device scratch ----------------
__device__ unsigned long long g_selkey[BMAX * KNMS];  // sorted top-100 keys (conf bits | ~idx)
__device__ float g_dec[BMAX * KNMS * 6];              // decoded boxes, rank order

__device__ __forceinline__ float sigmoidf_(float x) {
    return 1.0f / (1.0f + expf(-x));
}
// monotone float->uint transform (order-preserving over all floats)
__device__ __forceinline__ unsigned fkey_(float x) {
    unsigned b = __float_as_uint(x);
    return (b & 0x80000000u) ? ~b : (b | 0x80000000u);
}

// ============================================================
// K1: per-image exact top-100. One block/image, 1024 threads.
// Logit-domain filter (no sigmoid in hot loop), ONE 4096-bin
// histogram pass, compact ~120 candidates, sigmoid only there,
// exact 64-bit conf-rank = stable sorted top-100.
// ============================================================
__global__ void __launch_bounds__(1024)
select_kernel(const float* __restrict__ o13, const float* __restrict__ o26,
              const float* __restrict__ o52, const float* __restrict__ thr_p, int B)
{
    const int b = blockIdx.x;
    const int tid = threadIdx.x;
    const int lane = tid & 31;

    __shared__ unsigned hist[NBIN];               // 16 KB
    __shared__ unsigned csum[128];
    __shared__ unsigned long long ckey[LCAP];
    __shared__ unsigned srank[LCAP];
    __shared__ unsigned long long selkey[KNMS];
    __shared__ int sh_cb, sh_kres, sh_P, sh_cnt;

    const float thr = *thr_p;
    const float lthr = logf(thr / (1.0f - thr)); // conf > thr  <=>  x > lthr

    // ---- 15 per-thread monotone logit keys in registers (0 = below thr) ----
    unsigned ub[15];
    {
        const float* b13 = o13 + (size_t)b * 255 * CS13;
        const float* b26 = o26 + (size_t)b * 255 * CS26;
        const float* b52 = o52 + (size_t)b * 255 * CS52;
        #pragma unroll
        for (int a = 0; a < 3; ++a) {
            const float* p13 = b13 + (size_t)a * 85 * CS13;
            const float* p26 = b26 + (size_t)a * 85 * CS26;
            const float* p52 = b52 + (size_t)a * 85 * CS52;
            {
                unsigned r = 0;
                if (tid < CS13) { float v = p13[tid]; if (v > lthr) r = fkey_(v); }
                ub[a * 5 + 0] = r;
            }
            {
                unsigned r = 0;
                if (tid < CS26) { float v = p26[tid]; if (v > lthr) r = fkey_(v); }
                ub[a * 5 + 1] = r;
            }
            #pragma unroll
            for (int j = 0; j < 3; ++j) {
                unsigned r = 0;
                int cell = j * 1024 + tid;
                if (cell < CS52) { float v = p52[cell]; if (v > lthr) r = fkey_(v); }
                ub[a * 5 + 2 + j] = r;
            }
        }
    }

    #pragma unroll
    for (int i = 0; i < NBIN / 1024; ++i) hist[tid + i * 1024] = 0u;
    if (tid == 0) { sh_cnt = 0; sh_cb = 0; sh_kres = 1; }
    __syncthreads();

    // ---- single histogram pass (12-bit monotone key) ----
    #pragma unroll
    for (int s = 0; s < 15; ++s)
        if (ub[s]) atomicAdd(&hist[ub[s] >> 20], 1u);
    __syncthreads();

    // ---- coarse sums: 128 blocks of 32 bins ----
    if (tid < 128) {
        unsigned s = 0;
        #pragma unroll
        for (int j = 0; j < 32; ++j) s += hist[tid * 32 + j];
        csum[tid] = s;
    }
    __syncthreads();

    // ---- warp 0: suffix-scan over 128 coarse blocks (4/lane) ----
    if (tid < 32) {
        unsigned cc[4];
        int T = 0;
        #pragma unroll
        for (int r = 0; r < 4; ++r) { cc[r] = csum[lane * 4 + r]; T += (int)cc[r]; }
        int S = T;
        #pragma unroll
        for (int off = 1; off < 32; off <<= 1) {
            int v = __shfl_down_sync(0xffffffffu, S, off);
            if (lane + off < 32) S += v;
        }
        int Snext = __shfl_down_sync(0xffffffffu, S, 1);
        if (lane == 31) Snext = 0;
        if (S >= KNMS && Snext < KNMS) {
            int rem = Snext;
            #pragma unroll
            for (int r = 3; r >= 0; --r) {
                if (rem + (int)cc[r] >= KNMS) {
                    sh_cb = lane * 4 + r;
                    sh_kres = KNMS - rem;
                    break;
                }
                rem += (int)cc[r];
            }
        }
    }
    __syncthreads();
    // ---- fine scan inside the crossing block (32 bins, thread 0) ----
    if (tid == 0) {
        int cb = sh_cb, kres = sh_kres, rem = 0, P = cb * 32;
        for (int q = 31; q >= 0; --q) {
            rem += (int)hist[cb * 32 + q];
            if (rem >= kres) { P = cb * 32 + q; break; }
        }
        sh_P = P;
    }
    if (tid < LCAP) { ckey[tid] = 0ull; srank[tid] = 0u; }
    if (tid < KNMS) selkey[tid] = 0ull;
    __syncthreads();
    const unsigned P = (unsigned)sh_P;

    // ---- compact candidates (bin >= P); sigmoid ONLY here ----
    #pragma unroll
    for (int s = 0; s < 15; ++s) {
        unsigned u = ub[s];
        if (u && (u >> 20) >= P) {
            int a = s / 5, r = s % 5;
            int n;
            if (r == 0)      n = BASE13 + tid * 3 + a;
            else if (r == 1) n = BASE26 + tid * 3 + a;
            else             n = BASE52 + ((r - 2) * 1024 + tid) * 3 + a;
            float x = __uint_as_float((u & 0x80000000u) ? (u ^ 0x80000000u) : ~u);
            float conf = sigmoidf_(x);
            int pos = atomicAdd(&sh_cnt, 1);
            if (pos < LCAP)
                ckey[pos] = ((unsigned long long)__float_as_uint(conf) << 32)
                            | (unsigned)(~(unsigned)n);
        }
    }
    __syncthreads();
    int cnt = sh_cnt; if (cnt > LCAP) cnt = LCAP;
    const int nslice = (cnt + 63) >> 6;

    // ---- exact rank on conf keys; slice uniform per warp-group ----
    {
        int slice = tid >> 8;             // 0..3, uniform across 8 warps
        int e = tid & 255;
        if (slice < nslice) {
            unsigned long long mykey = ckey[e];
            if (mykey != 0ull) {
                int c2 = 0;
                int j0 = slice * 64;
                #pragma unroll 16
                for (int j = 0; j < 64; ++j)
                    if (ckey[j0 + j] > mykey) c2++;
                if (c2) atomicAdd(&srank[e], (unsigned)c2);
            }
        }
    }
    __syncthreads();
    if (tid < LCAP) {
        unsigned long long k = ckey[tid];
        if (k != 0ull) {
            unsigned r = srank[tid];
            if (r < KNMS) selkey[r] = k;
        }
    }
    __syncthreads();
    if (tid < KNMS) g_selkey[b * KNMS + tid] = selkey[tid];
}

// ============================================================
// K2: decode gather — 416 CTAs for chip-wide MLP. 128 thr/block,
// one warp handles 2 boxes; all scattered loads issued up front.
// ============================================================
__device__ __forceinline__ void decode_emit(
    int b, int box, int lane, float v0, float v1, float v2,
    int x, int y, float strd, float aw, float ah)
{
    float ch0 = __shfl_sync(0xffffffffu, v0, 0);
    float ch1 = __shfl_sync(0xffffffffu, v0, 1);
    float ch2 = __shfl_sync(0xffffffffu, v0, 2);
    float ch3 = __shfl_sync(0xffffffffu, v0, 3);
    float ch4 = __shfl_sync(0xffffffffu, v0, 4);

    float bv = -3.402823466e+38f;
    int bi = 0x7FFFFFFF;
    if (lane >= 5)            { bv = v0; bi = lane - 5; }
    if (v1 > bv)              { bv = v1; bi = lane + 27; }
    if (lane < 21 && v2 > bv) { bv = v2; bi = lane + 59; }
    #pragma unroll
    for (int off = 16; off; off >>= 1) {
        float ov = __shfl_xor_sync(0xffffffffu, bv, off);
        int oi = __shfl_xor_sync(0xffffffffu, bi, off);
        if (ov > bv || (ov == bv && oi < bi)) { bv = ov; bi = oi; }
    }

    if (lane == 0) {
        float conf = sigmoidf_(ch0);
        float sx = sigmoidf_(ch1);
        float sy = sigmoidf_(ch2);
        float ww = expf(ch3) * aw;
        float hh = expf(ch4) * ah;
        float ox = ((float)x + sx) * strd;
        float oy = ((float)y + sy) * strd;
        float* d = g_dec + ((size_t)b * KNMS + box) * 6;
        d[0] = ox - 0.5f * ww;
        d[1] = oy - 0.5f * hh;
        d[2] = ox + 0.5f * ww;
        d[3] = oy + 0.5f * hh;
        d[4] = (float)bi;
        d[5] = conf;
    }
}

__global__ void __launch_bounds__(128)
decode_kernel(const float* __restrict__ o13, const float* __restrict__ o26,
              const float* __restrict__ o52, const float* __restrict__ anc, int B)
{
    int blk = blockIdx.x;
    int b = blk / DBLK, chunk = blk - b * DBLK;
    int wid = threadIdx.x >> 5, lane = threadIdx.x & 31;
    int pi = chunk * 4 + wid;                 // 0..51
    if (pi >= 52) return;
    int boxA = pi;
    int boxB = pi + 52;
    bool hasB = (boxB < KNMS);

    unsigned idxA = ~(unsigned)(g_selkey[b * KNMS + boxA] & 0xFFFFFFFFu);
    int SA, csA, baseA; float strdA; const float* inA; const float* arowA;
    if (idxA < BASE26)      { SA = 13; csA = CS13; baseA = BASE13; strdA = 32.f; inA = o13; arowA = anc + 0; }
    else if (idxA < BASE52) { SA = 26; csA = CS26; baseA = BASE26; strdA = 16.f; inA = o26; arowA = anc + 6; }
    else                    { SA = 52; csA = CS52; baseA = BASE52; strdA = 8.f;  inA = o52; arowA = anc + 12; }
    int mA = (int)idxA - baseA;
    int cellA = mA / 3, aA = mA - cellA * 3;
    int yA = cellA / SA, xA = cellA - yA * SA;
    const float* pA = inA + ((size_t)b * 255 + (size_t)aA * 85) * csA + cellA;

    unsigned idxB = hasB ? ~(unsigned)(g_selkey[b * KNMS + boxB] & 0xFFFFFFFFu) : idxA;
    int SB, csB, baseB; float strdB; const float* inB; const float* arowB;
    if (idxB < BASE26)      { SB = 13; csB = CS13; baseB = BASE13; strdB = 32.f; inB = o13; arowB = anc + 0; }
    else if (idxB < BASE52) { SB = 26; csB = CS26; baseB = BASE26; strdB = 16.f; inB = o26; arowB = anc + 6; }
    else                    { SB = 52; csB = CS52; baseB = BASE52; strdB = 8.f;  inB = o52; arowB = anc + 12; }
    int mB = (int)idxB - baseB;
    int cellB = mB / 3, aB = mB - cellB * 3;
    int yB = cellB / SB, xB = cellB - yB * SB;
    const float* pB = inB + ((size_t)b * 255 + (size_t)aB * 85) * csB + cellB;

    float a0 = pA[(size_t)lane * csA];
    float a1 = pA[(size_t)(lane + 32) * csA];
    float a2 = (lane < 21) ? pA[(size_t)(lane + 64) * csA] : 0.f;
    float b0 = pB[(size_t)lane * csB];
    float b1 = pB[(size_t)(lane + 32) * csB];
    float b2 = (lane < 21) ? pB[(size_t)(lane + 64) * csB] : 0.f;

    decode_emit(b, boxA, lane, a0, a1, a2, xA, yA, strdA,
                arowA[aA * 2 + 0], arowA[aA * 2 + 1]);
    if (hasB)
        decode_emit(b, boxB, lane, b0, b1, b2, xB, yB, strdB,
                    arowB[aB * 2 + 0], arowB[aB * 2 + 1]);
}

// ============================================================
// K3: NMS — one block/image, 128 thr. Boxes are L2-hot.
// ============================================================
__global__ void __launch_bounds__(128)
nms_kernel(float* __restrict__ out, int B)
{
    const int b = blockIdx.x;
    const int t = threadIdx.x;

    __shared__ float sbox[KNMS * 6];
    __shared__ float sarea[KNMS];
    __shared__ unsigned sup[KNMS * 4];
    __shared__ unsigned keep0w[4], keepw[4];

    if (t < 4) keep0w[t] = 0u;
    for (int i = t; i < KNMS * 6; i += 128) sbox[i] = g_dec[(size_t)b * KNMS * 6 + i];
    __syncthreads();
    if (t < KNMS) {
        sarea[t] = fmaxf(sbox[t * 6 + 2] - sbox[t * 6 + 0], 0.f) *
                   fmaxf(sbox[t * 6 + 3] - sbox[t * 6 + 1], 0.f);
        if ((unsigned)(g_selkey[b * KNMS + t] >> 32) != 0u)
            atomicOr(&keep0w[t >> 5], 1u << (t & 31));
    }
    __syncthreads();

    for (int w = t; w < KNMS * 4; w += 128) {
        int i = w >> 2, c = w & 3;
        unsigned m = 0;
        float ix1 = sbox[i * 6 + 0], iy1 = sbox[i * 6 + 1];
        float ix2 = sbox[i * 6 + 2], iy2 = sbox[i * 6 + 3];
        float icls = sbox[i * 6 + 4], iar = sarea[i];
        int j0 = c * 32;
        #pragma unroll 8
        for (int jj = 0; jj < 32; ++jj) {
            int j = j0 + jj;
            if (j > i && j < KNMS && sbox[j * 6 + 4] == icls) {
                float x1 = fmaxf(ix1, sbox[j * 6 + 0]);
                float y1 = fmaxf(iy1, sbox[j * 6 + 1]);
                float x2 = fminf(ix2, sbox[j * 6 + 2]);
                float y2 = fminf(iy2, sbox[j * 6 + 3]);
                float inter = fmaxf(x2 - x1, 0.f) * fmaxf(y2 - y1, 0.f);
                float uni = iar + sarea[j] - inter;
                if (inter / fmaxf(uni, 1e-9f) > IOU_THR) m |= (1u << jj);
            }
        }
        sup[w] = m;
    }
    __syncthreads();

    if (t == 0) {
        unsigned k0 = keep0w[0], k1 = keep0w[1], k2 = keep0w[2], k3 = keep0w[3];
        unsigned n0 = sup[0], n1 = sup[1], n2 = sup[2], n3 = sup[3];
        for (int i = 0; i < KNMS; ++i) {
            unsigned s0 = n0, s1 = n1, s2 = n2, s3 = n3;
            if (i + 1 < KNMS) {
                n0 = sup[(i + 1) * 4 + 0];
                n1 = sup[(i + 1) * 4 + 1];
                n2 = sup[(i + 1) * 4 + 2];
                n3 = sup[(i + 1) * 4 + 3];
            }
            unsigned word = (i < 32) ? k0 : (i < 64) ? k1 : (i < 96) ? k2 : k3;
            unsigned msk = (unsigned)(-(int)((word >> (i & 31)) & 1u));
            k0 &= ~(s0 & msk);
            k1 &= ~(s1 & msk);
            k2 &= ~(s2 & msk);
            k3 &= ~(s3 & msk);
        }
        keepw[0] = k0; keepw[1] = k1; keepw[2] = k2; keepw[3] = k3;
    }
    __syncthreads();

    float* out_sel = out;
    float* out_keep = out + (size_t)B * KNMS * 6;
    if (t < KNMS) {
        #pragma unroll
        for (int c = 0; c < 6; ++c)
            out_sel[((size_t)b * KNMS + t) * 6 + c] = sbox[t * 6 + c];
        out_keep[(size_t)b * KNMS + t] =
            ((keepw[t >> 5] >> (t & 31)) & 1u) ? 1.0f : 0.0f;
    }
}

// ============================================================
extern "C" void kernel_launch(void* const* d_in, const int* in_sizes, int n_in,
                              void* d_out, int out_size)
{
    const float* o13 = (const float*)d_in[0];
    const float* o26 = (const float*)d_in[1];
    const float* o52 = (const float*)d_in[2];
    const float* anc = (const float*)d_in[3];   // [3,3,2]
    const float* thr = (const float*)d_in[4];   // scalar

    int B = in_sizes[0] / (255 * CS13);
    if (B > BMAX) B = BMAX;
    float* out = (float*)d_out;

    select_kernel<<<B, 1024>>>(o13, o26, o52, thr, B);
    decode_kernel<<<B * DBLK, 128>>>(o13, o26, o52, anc, B);
    nms_kernel<<<B, 128>>>(out, B);
}

// round 12
// speedup vs baseline: 1.6855x; 1.3265x over previous
#include <cuda_runtime.h>
#include <cstdint>

// ---------------- problem constants ----------------
#define KNMS 100
#define BMAX 32
#define IOU_THR 0.3f

#define CS13 169
#define CS26 676
#define CS52 2704
#define N52V 676            // CS52/4 float4 per 52-scale anchor plane
#define BASE13 0
#define BASE26 507
#define BASE52 2535
#define LCAP 256            // compact candidate list capacity
#define DBLK 13             // decode blocks per image
#define NBIN 4096           // 12-bit monotone-key histogram

// ---------------- device scratch ----------------
__device__ unsigned long long g_selkey[BMAX * KNMS];  // sorted top-100 keys (conf bits | ~idx)
__device__ float g_dec[BMAX * KNMS * 6];              // decoded boxes, rank order

__device__ __forceinline__ float sigmoidf_(float x) {
    return 1.0f / (1.0f + expf(-x));
}
// monotone float->uint transform (order-preserving)
__device__ __forceinline__ unsigned fkey_(float x) {
    unsigned b = __float_as_uint(x);
    return (b & 0x80000000u) ? ~b : (b | 0x80000000u);
}

// ============================================================
// K1: per-image exact top-100. One block/image, 1024 threads.
// Phase A: stream conf values (float4 on 52-scale), histogram only.
// Threshold pick: vectorized coarse sums + warp-parallel fine scan.
// Phase B: re-stream (L2-hot), compact candidates, sigmoid there,
// exact 64-bit conf-rank = stable sorted top-100.
// ============================================================
__global__ void __launch_bounds__(1024)
select_kernel(const float* __restrict__ o13, const float* __restrict__ o26,
              const float* __restrict__ o52, const float* __restrict__ thr_p, int B)
{
    const int b = blockIdx.x;
    const int tid = threadIdx.x;
    const int lane = tid & 31;

    __shared__ unsigned hist[NBIN];               // 16 KB
    __shared__ unsigned psum[1024];               // 4 KB
    __shared__ unsigned csum[128];
    __shared__ unsigned long long ckey[LCAP];
    __shared__ unsigned srank[LCAP];
    __shared__ unsigned long long selkey[KNMS];
    __shared__ int sh_cb, sh_kres, sh_P, sh_cnt;

    const float thr = *thr_p;
    const float lthr = logf(thr / (1.0f - thr)); // conf > thr  <=>  logit > lthr

    const float* b13 = o13 + (size_t)b * 255 * CS13;
    const float* b26 = o26 + (size_t)b * 255 * CS26;
    const float* b52 = o52 + (size_t)b * 255 * CS52;

    // zero histogram (one uint4 store per thread)
    ((uint4*)hist)[tid] = make_uint4(0u, 0u, 0u, 0u);
    if (tid == 0) sh_cnt = 0;
    __syncthreads();

    // ---- Phase A: stream + histogram (keep nothing) ----
    #pragma unroll
    for (int a = 0; a < 3; ++a) {
        const float* p13 = b13 + (size_t)a * 85 * CS13;
        const float* p26 = b26 + (size_t)a * 85 * CS26;
        const float* p52 = b52 + (size_t)a * 85 * CS52;
        if (tid < CS13) {
            float v = p13[tid];
            if (v > lthr) atomicAdd(&hist[fkey_(v) >> 20], 1u);
        }
        if (tid < CS26) {
            float v = p26[tid];
            if (v > lthr) atomicAdd(&hist[fkey_(v) >> 20], 1u);
        }
        if (tid < N52V) {
            float4 q = ((const float4*)p52)[tid];
            if (q.x > lthr) atomicAdd(&hist[fkey_(q.x) >> 20], 1u);
            if (q.y > lthr) atomicAdd(&hist[fkey_(q.y) >> 20], 1u);
            if (q.z > lthr) atomicAdd(&hist[fkey_(q.z) >> 20], 1u);
            if (q.w > lthr) atomicAdd(&hist[fkey_(q.w) >> 20], 1u);
        }
    }
    __syncthreads();

    // ---- partial sums: 1024 x (4 bins via one uint4) ----
    {
        uint4 h4 = ((uint4*)hist)[tid];
        psum[tid] = h4.x + h4.y + h4.z + h4.w;
    }
    __syncthreads();
    // ---- coarse sums: 128 x (8 psum via two uint4) ----
    if (tid < 128) {
        uint4 a0 = ((uint4*)psum)[tid * 2];
        uint4 a1 = ((uint4*)psum)[tid * 2 + 1];
        csum[tid] = a0.x + a0.y + a0.z + a0.w + a1.x + a1.y + a1.z + a1.w;
    }
    __syncthreads();

    // ---- warp 0: coarse pick (suffix-scan over 128 blocks), then
    //      warp-parallel fine pick inside the crossing block ----
    if (tid < 32) {
        unsigned cc[4];
        int T = 0;
        #pragma unroll
        for (int r = 0; r < 4; ++r) { cc[r] = csum[lane * 4 + r]; T += (int)cc[r]; }
        int S = T;
        #pragma unroll
        for (int off = 1; off < 32; off <<= 1) {
            int v = __shfl_down_sync(0xffffffffu, S, off);
            if (lane + off < 32) S += v;
        }
        int Snext = __shfl_down_sync(0xffffffffu, S, 1);
        if (lane == 31) Snext = 0;
        if (S >= KNMS && Snext < KNMS) {
            int rem = Snext;
            #pragma unroll
            for (int r = 3; r >= 0; --r) {
                if (rem + (int)cc[r] >= KNMS) {
                    sh_cb = lane * 4 + r;
                    sh_kres = KNMS - rem;
                    break;
                }
                rem += (int)cc[r];
            }
        }
        __syncwarp();
        int cb = sh_cb, kres = sh_kres;
        // fine: lane q owns bin cb*32+q
        unsigned h = hist[cb * 32 + lane];
        int S2 = (int)h;
        #pragma unroll
        for (int off = 1; off < 32; off <<= 1) {
            int v = __shfl_down_sync(0xffffffffu, S2, off);
            if (lane + off < 32) S2 += v;
        }
        int S2n = __shfl_down_sync(0xffffffffu, S2, 1);
        if (lane == 31) S2n = 0;
        if (S2 >= kres && S2n < kres) sh_P = cb * 32 + lane;
    }
    if (tid < LCAP) { ckey[tid] = 0ull; srank[tid] = 0u; }
    if (tid < KNMS) selkey[tid] = 0ull;
    __syncthreads();
    const unsigned P = (unsigned)sh_P;

    // ---- Phase B: re-stream (L2-hot), compact candidates ----
    #pragma unroll
    for (int a = 0; a < 3; ++a) {
        const float* p13 = b13 + (size_t)a * 85 * CS13;
        const float* p26 = b26 + (size_t)a * 85 * CS26;
        const float* p52 = b52 + (size_t)a * 85 * CS52;
        if (tid < CS13) {
            float v = p13[tid];
            if (v > lthr) {
                unsigned u = fkey_(v);
                if ((u >> 20) >= P) {
                    int n = BASE13 + tid * 3 + a;
                    int pos = atomicAdd(&sh_cnt, 1);
                    if (pos < LCAP)
                        ckey[pos] = ((unsigned long long)__float_as_uint(sigmoidf_(v)) << 32)
                                    | (unsigned)(~(unsigned)n);
                }
            }
        }
        if (tid < CS26) {
            float v = p26[tid];
            if (v > lthr) {
                unsigned u = fkey_(v);
                if ((u >> 20) >= P) {
                    int n = BASE26 + tid * 3 + a;
                    int pos = atomicAdd(&sh_cnt, 1);
                    if (pos < LCAP)
                        ckey[pos] = ((unsigned long long)__float_as_uint(sigmoidf_(v)) << 32)
                                    | (unsigned)(~(unsigned)n);
                }
            }
        }
        if (tid < N52V) {
            float4 q = ((const float4*)p52)[tid];
            float vv[4] = {q.x, q.y, q.z, q.w};
            #pragma unroll
            for (int j = 0; j < 4; ++j) {
                float v = vv[j];
                if (v > lthr) {
                    unsigned u = fkey_(v);
                    if ((u >> 20) >= P) {
                        int n = BASE52 + (tid * 4 + j) * 3 + a;
                        int pos = atomicAdd(&sh_cnt, 1);
                        if (pos < LCAP)
                            ckey[pos] = ((unsigned long long)__float_as_uint(sigmoidf_(v)) << 32)
                                        | (unsigned)(~(unsigned)n);
                    }
                }
            }
        }
    }
    __syncthreads();
    int cnt = sh_cnt; if (cnt > LCAP) cnt = LCAP;
    const int nslice = (cnt + 63) >> 6;

    // ---- exact rank on conf keys; slice uniform per warp-group ----
    {
        int slice = tid >> 8;             // 0..3, uniform across 8 warps
        int e = tid & 255;
        if (slice < nslice) {
            unsigned long long mykey = ckey[e];
            if (mykey != 0ull) {
                int c2 = 0;
                int j0 = slice * 64;
                #pragma unroll 16
                for (int j = 0; j < 64; ++j)
                    if (ckey[j0 + j] > mykey) c2++;
                if (c2) atomicAdd(&srank[e], (unsigned)c2);
            }
        }
    }
    __syncthreads();
    if (tid < LCAP) {
        unsigned long long k = ckey[tid];
        if (k != 0ull) {
            unsigned r = srank[tid];
            if (r < KNMS) selkey[r] = k;
        }
    }
    __syncthreads();
    if (tid < KNMS) g_selkey[b * KNMS + tid] = selkey[tid];
}

// ============================================================
// K2: decode gather — 416 CTAs for chip-wide MLP. 128 thr/block,
// one warp handles 2 boxes; all scattered loads issued up front.
// ============================================================
__device__ __forceinline__ void decode_emit(
    int b, int box, int lane, float v0, float v1, float v2,
    int x, int y, float strd, float aw, float ah)
{
    float ch0 = __shfl_sync(0xffffffffu, v0, 0);
    float ch1 = __shfl_sync(0xffffffffu, v0, 1);
    float ch2 = __shfl_sync(0xffffffffu, v0, 2);
    float ch3 = __shfl_sync(0xffffffffu, v0, 3);
    float ch4 = __shfl_sync(0xffffffffu, v0, 4);

    float bv = -3.402823466e+38f;
    int bi = 0x7FFFFFFF;
    if (lane >= 5)            { bv = v0; bi = lane - 5; }
    if (v1 > bv)              { bv = v1; bi = lane + 27; }
    if (lane < 21 && v2 > bv) { bv = v2; bi = lane + 59; }
    #pragma unroll
    for (int off = 16; off; off >>= 1) {
        float ov = __shfl_xor_sync(0xffffffffu, bv, off);
        int oi = __shfl_xor_sync(0xffffffffu, bi, off);
        if (ov > bv || (ov == bv && oi < bi)) { bv = ov; bi = oi; }
    }

    if (lane == 0) {
        float conf = sigmoidf_(ch0);
        float sx = sigmoidf_(ch1);
        float sy = sigmoidf_(ch2);
        float ww = expf(ch3) * aw;
        float hh = expf(ch4) * ah;
        float ox = ((float)x + sx) * strd;
        float oy = ((float)y + sy) * strd;
        float* d = g_dec + ((size_t)b * KNMS + box) * 6;
        d[0] = ox - 0.5f * ww;
        d[1] = oy - 0.5f * hh;
        d[2] = ox + 0.5f * ww;
        d[3] = oy + 0.5f * hh;
        d[4] = (float)bi;
        d[5] = conf;
    }
}

__global__ void __launch_bounds__(128)
decode_kernel(const float* __restrict__ o13, const float* __restrict__ o26,
              const float* __restrict__ o52, const float* __restrict__ anc, int B)
{
    int blk = blockIdx.x;
    int b = blk / DBLK, chunk = blk - b * DBLK;
    int wid = threadIdx.x >> 5, lane = threadIdx.x & 31;
    int pi = chunk * 4 + wid;                 // 0..51
    if (pi >= 52) return;
    int boxA = pi;
    int boxB = pi + 52;
    bool hasB = (boxB < KNMS);

    unsigned idxA = ~(unsigned)(g_selkey[b * KNMS + boxA] & 0xFFFFFFFFu);
    int SA, csA, baseA; float strdA; const float* inA; const float* arowA;
    if (idxA < BASE26)      { SA = 13; csA = CS13; baseA = BASE13; strdA = 32.f; inA = o13; arowA = anc + 0; }
    else if (idxA < BASE52) { SA = 26; csA = CS26; baseA = BASE26; strdA = 16.f; inA = o26; arowA = anc + 6; }
    else                    { SA = 52; csA = CS52; baseA = BASE52; strdA = 8.f;  inA = o52; arowA = anc + 12; }
    int mA = (int)idxA - baseA;
    int cellA = mA / 3, aA = mA - cellA * 3;
    int yA = cellA / SA, xA = cellA - yA * SA;
    const float* pA = inA + ((size_t)b * 255 + (size_t)aA * 85) * csA + cellA;

    unsigned idxB = hasB ? ~(unsigned)(g_selkey[b * KNMS + boxB] & 0xFFFFFFFFu) : idxA;
    int SB, csB, baseB; float strdB; const float* inB; const float* arowB;
    if (idxB < BASE26)      { SB = 13; csB = CS13; baseB = BASE13; strdB = 32.f; inB = o13; arowB = anc + 0; }
    else if (idxB < BASE52) { SB = 26; csB = CS26; baseB = BASE26; strdB = 16.f; inB = o26; arowB = anc + 6; }
    else                    { SB = 52; csB = CS52; baseB = BASE52; strdB = 8.f;  inB = o52; arowB = anc + 12; }
    int mB = (int)idxB - baseB;
    int cellB = mB / 3, aB = mB - cellB * 3;
    int yB = cellB / SB, xB = cellB - yB * SB;
    const float* pB = inB + ((size_t)b * 255 + (size_t)aB * 85) * csB + cellB;

    float a0 = pA[(size_t)lane * csA];
    float a1 = pA[(size_t)(lane + 32) * csA];
    float a2 = (lane < 21) ? pA[(size_t)(lane + 64) * csA] : 0.f;
    float b0 = pB[(size_t)lane * csB];
    float b1 = pB[(size_t)(lane + 32) * csB];
    float b2 = (lane < 21) ? pB[(size_t)(lane + 64) * csB] : 0.f;

    decode_emit(b, boxA, lane, a0, a1, a2, xA, yA, strdA,
                arowA[aA * 2 + 0], arowA[aA * 2 + 1]);
    if (hasB)
        decode_emit(b, boxB, lane, b0, b1, b2, xB, yB, strdB,
                    arowB[aB * 2 + 0], arowB[aB * 2 + 1]);
}

// ============================================================
// K3: NMS — one block/image, 512 thr (sup build in one pass).
// ============================================================
__global__ void __launch_bounds__(512)
nms_kernel(float* __restrict__ out, int B)
{
    const int b = blockIdx.x;
    const int t = threadIdx.x;

    __shared__ float sbox[KNMS * 6];
    __shared__ float sarea[KNMS];
    __shared__ unsigned sup[KNMS * 4];
    __shared__ unsigned keep0w[4], keepw[4];

    if (t < 4) keep0w[t] = 0u;
    for (int i = t; i < KNMS * 6; i += 512) sbox[i] = g_dec[(size_t)b * KNMS * 6 + i];
    __syncthreads();
    if (t < KNMS) {
        sarea[t] = fmaxf(sbox[t * 6 + 2] - sbox[t * 6 + 0], 0.f) *
                   fmaxf(sbox[t * 6 + 3] - sbox[t * 6 + 1], 0.f);
        if ((unsigned)(g_selkey[b * KNMS + t] >> 32) != 0u)
            atomicOr(&keep0w[t >> 5], 1u << (t & 31));
    }
    __syncthreads();

    if (t < KNMS * 4) {
        int i = t >> 2, c = t & 3;
        unsigned m = 0;
        float ix1 = sbox[i * 6 + 0], iy1 = sbox[i * 6 + 1];
        float ix2 = sbox[i * 6 + 2], iy2 = sbox[i * 6 + 3];
        float icls = sbox[i * 6 + 4], iar = sarea[i];
        int j0 = c * 32;
        #pragma unroll 8
        for (int jj = 0; jj < 32; ++jj) {
            int j = j0 + jj;
            if (j > i && j < KNMS && sbox[j * 6 + 4] == icls) {
                float x1 = fmaxf(ix1, sbox[j * 6 + 0]);
                float y1 = fmaxf(iy1, sbox[j * 6 + 1]);
                float x2 = fminf(ix2, sbox[j * 6 + 2]);
                float y2 = fminf(iy2, sbox[j * 6 + 3]);
                float inter = fmaxf(x2 - x1, 0.f) * fmaxf(y2 - y1, 0.f);
                float uni = iar + sarea[j] - inter;
                if (inter / fmaxf(uni, 1e-9f) > IOU_THR) m |= (1u << jj);
            }
        }
        sup[t] = m;
    }
    __syncthreads();

    if (t == 0) {
        unsigned k0 = keep0w[0], k1 = keep0w[1], k2 = keep0w[2], k3 = keep0w[3];
        unsigned n0 = sup[0], n1 = sup[1], n2 = sup[2], n3 = sup[3];
        for (int i = 0; i < KNMS; ++i) {
            unsigned s0 = n0, s1 = n1, s2 = n2, s3 = n3;
            if (i + 1 < KNMS) {
                n0 = sup[(i + 1) * 4 + 0];
                n1 = sup[(i + 1) * 4 + 1];
                n2 = sup[(i + 1) * 4 + 2];
                n3 = sup[(i + 1) * 4 + 3];
            }
            unsigned word = (i < 32) ? k0 : (i < 64) ? k1 : (i < 96) ? k2 : k3;
            unsigned msk = (unsigned)(-(int)((word >> (i & 31)) & 1u));
            k0 &= ~(s0 & msk);
            k1 &= ~(s1 & msk);
            k2 &= ~(s2 & msk);
            k3 &= ~(s3 & msk);
        }
        keepw[0] = k0; keepw[1] = k1; keepw[2] = k2; keepw[3] = k3;
    }
    __syncthreads();

    float* out_sel = out;
    float* out_keep = out + (size_t)B * KNMS * 6;
    if (t < KNMS) {
        #pragma unroll
        for (int c = 0; c < 6; ++c)
            out_sel[((size_t)b * KNMS + t) * 6 + c] = sbox[t * 6 + c];
        out_keep[(size_t)b * KNMS + t] =
            ((keepw[t >> 5] >> (t & 31)) & 1u) ? 1.0f : 0.0f;
    }
}

// ============================================================
extern "C" void kernel_launch(void* const* d_in, const int* in_sizes, int n_in,
                              void* d_out, int out_size)
{
    const float* o13 = (const float*)d_in[0];
    const float* o26 = (const float*)d_in[1];
    const float* o52 = (const float*)d_in[2];
    const float* anc = (const float*)d_in[3];   // [3,3,2]
    const float* thr = (const float*)d_in[4];   // scalar

    int B = in_sizes[0] / (255 * CS13);
    if (B > BMAX) B = BMAX;
    float* out = (float*)d_out;

    select_kernel<<<B, 1024>>>(o13, o26, o52, thr, B);
    decode_kernel<<<B * DBLK, 128>>>(o13, o26, o52, anc, B);
    nms_kernel<<<B, 512>>>(out, B);
}